// round 6
// baseline (speedup 1.0000x reference)
#include <cuda_runtime.h>
#include <math.h>

#define TT  2048
#define BB  2
#define DD  512
#define NHH 8

#define OFF_INW   0
#define OFF_OUTW  786432
#define OFF_POSW  1048576
#define OFF_INB   1310720
#define OFF_OUTB  1312256
#define OFF_POSB  1312768
#define OFF_RWB   1313280
#define OFF_RRB   1313792
#define N_W       1314304

typedef unsigned long long u64;

__device__ __forceinline__ void upk2(u64 v, float& lo, float& hi) {
    asm("mov.b64 {%0, %1}, %2;" : "=f"(lo), "=f"(hi) : "l"(v));
}
__device__ __forceinline__ u64 ffma2(u64 a, u64 b, u64 c) {
    u64 d; asm("fma.rn.f32x2 %0, %1, %2, %3;" : "=l"(d) : "l"(a), "l"(b), "l"(c));
    return d;
}
__device__ __forceinline__ u64 fmul2(u64 a, u64 b) {
    u64 d; asm("mul.rn.f32x2 %0, %1, %2;" : "=l"(d) : "l"(a), "l"(b)); return d;
}
__device__ __forceinline__ u64 splat2(float x) {
    u64 r; asm("mov.b64 %0, {%1, %1};" : "=l"(r) : "f"(x)); return r;
}
__device__ __forceinline__ u64 pk2(float lo, float hi) {
    u64 r; asm("mov.b64 %0, {%1, %2};" : "=l"(r) : "f"(lo), "f"(hi)); return r;
}

__device__ float g_w[N_W];
__device__ float g_qkv[(size_t)TT * BB * 3 * DD];
__device__ float g_r[(size_t)TT * DD];
__device__ float g_att[(size_t)TT * BB * DD];

// ---------------------------------------------------------------------------
__global__ void k_sample_w(const float* __restrict__ mu,
                           const float* __restrict__ rho,
                           const float* __restrict__ eps,
                           float* __restrict__ w, int n) {
    int i = blockIdx.x * blockDim.x + threadIdx.x;
    if (i < n) {
        float r = rho[i];
        float sp = (r > 20.f) ? r : log1pf(expf(r));
        w[i] = fmaf(sp, eps[i], mu[i]);
    }
}

// ---------------------------------------------------------------------------
// GEMM: C[M,N] = A[M,K] @ W[N,K]^T + bias. 128x128 tile, 8x8 micro,
// j-packed FFMA2 (BsT transposed in smem). M,N %128==0, K %32==0.
// ---------------------------------------------------------------------------
__global__ __launch_bounds__(256, 2)
void k_gemm(const float* __restrict__ A, const float* __restrict__ W,
            const float* __restrict__ bias, float* __restrict__ C,
            int M, int N, int K) {
    __shared__ float As[128 * 32];
    __shared__ float BsT[32 * 132];
    const int tid = threadIdx.x, tx = tid & 15, ty = tid >> 4;
    const int m0 = blockIdx.y * 128, n0 = blockIdx.x * 128;

    u64 acc[8][4];
#pragma unroll
    for (int u = 0; u < 8; u++)
#pragma unroll
        for (int p = 0; p < 4; p++) acc[u][p] = 0ull;

    for (int k0 = 0; k0 < K; k0 += 32) {
        __syncthreads();
#pragma unroll
        for (int p = 0; p < 4; p++) {
            int idx = p * 256 + tid;
            int mi = idx >> 3, k4 = idx & 7;
            *(float4*)(As + mi * 32 + 4 * k4) =
                *(const float4*)(A + (size_t)(m0 + mi) * K + k0 + 4 * k4);
            float4 wv = *(const float4*)(W + (size_t)(n0 + mi) * K + k0 + 4 * k4);
            BsT[(4 * k4 + 0) * 132 + mi] = wv.x;
            BsT[(4 * k4 + 1) * 132 + mi] = wv.y;
            BsT[(4 * k4 + 2) * 132 + mi] = wv.z;
            BsT[(4 * k4 + 3) * 132 + mi] = wv.w;
        }
        __syncthreads();
#pragma unroll 2
        for (int k4 = 0; k4 < 8; k4++) {
            float4 av[8];
#pragma unroll
            for (int u = 0; u < 8; u++)
                av[u] = *(const float4*)(As + (8 * ty + u) * 32 + 4 * k4);
#pragma unroll
            for (int kk = 0; kk < 4; kk++) {
                const float* bp = BsT + (4 * k4 + kk) * 132;
                ulonglong2 b0 = *(const ulonglong2*)(bp + 4 * tx);
                ulonglong2 b1 = *(const ulonglong2*)(bp + 64 + 4 * tx);
#pragma unroll
                for (int u = 0; u < 8; u++) {
                    u64 as = splat2(((const float*)&av[u])[kk]);
                    acc[u][0] = ffma2(as, b0.x, acc[u][0]);
                    acc[u][1] = ffma2(as, b0.y, acc[u][1]);
                    acc[u][2] = ffma2(as, b1.x, acc[u][2]);
                    acc[u][3] = ffma2(as, b1.y, acc[u][3]);
                }
            }
        }
    }

    float4 ba = *(const float4*)(bias + n0 + 4 * tx);
    float4 bb = *(const float4*)(bias + n0 + 64 + 4 * tx);
#pragma unroll
    for (int u = 0; u < 8; u++) {
        int m = m0 + 8 * ty + u;
        float c0, c1, c2, c3, c4, c5, c6, c7;
        upk2(acc[u][0], c0, c1); upk2(acc[u][1], c2, c3);
        upk2(acc[u][2], c4, c5); upk2(acc[u][3], c6, c7);
        *(float4*)(C + (size_t)m * N + n0 + 4 * tx) =
            make_float4(c0 + ba.x, c1 + ba.y, c2 + ba.z, c3 + ba.w);
        *(float4*)(C + (size_t)m * N + n0 + 64 + 4 * tx) =
            make_float4(c4 + bb.x, c5 + bb.y, c6 + bb.z, c7 + bb.w);
    }
}

// ---------------------------------------------------------------------------
// Flash attention, fused rel-shift. 64x64 tile, 128 threads, 8(i)x4(j) micro,
// k-packed FFMA2. score = 0.125*(qw·k + qw·r_dd + corr[dd]),
// dd = j-i+63 (tile-rel), corr = delta·r_dd, delta = rrb - rwb.
// ---------------------------------------------------------------------------
#define SMF 25216   // floats (100864 bytes)

__global__ __launch_bounds__(128, 2)
void k_flash(const float* __restrict__ qkv, const float* __restrict__ rbuf,
             const float* __restrict__ w, float* __restrict__ att) {
    const int combo = blockIdx.x, b = combo >> 3, n = combo & 7;
    const int it = 31 - (int)blockIdx.y;
    const int i0 = it * 64;
    const int tid = threadIdx.x, tx = tid & 15, ty = tid >> 4;   // ty 0..7

    extern __shared__ float sm[];
    float* qws = sm;             // [64][64] rows i, k-contig
    float* Ks  = sm + 4096;      // [64][64] swizzled, key j>>2
    float* Vs  = sm + 8192;      // [64][68]
    float* Ps  = sm + 12544;     // [64][68]
    float* Rs  = sm + 16896;     // [127][64] swizzled, key (dd>>2)&15
    float* delta = sm + 25024;   // [64]
    float* corr  = sm + 25088;   // [128]

    if (tid < 64)
        delta[tid] = w[OFF_RRB + n * 64 + tid] - w[OFF_RWB + n * 64 + tid];

#pragma unroll
    for (int p = 0; p < 8; p++) {
        int idx = p * 128 + tid;
        int i = idx >> 4, k4 = idx & 15;
        float4 qv = *(const float4*)(qkv + ((size_t)(i0 + i) * BB + b) * 1536 + n * 64 + 4 * k4);
        float4 bw = *(const float4*)(w + OFF_RWB + n * 64 + 4 * k4);
        *(float4*)(qws + i * 64 + 4 * k4) =
            make_float4(qv.x + bw.x, qv.y + bw.y, qv.z + bw.z, qv.w + bw.w);
    }

    const int rbase = 4 * tx - 8 * ty + 56;    // dd row at t=0 (>=0)
    float m_run[8], l_run[8];
    u64 o2[8][2];
#pragma unroll
    for (int u = 0; u < 8; u++) {
        m_run[u] = -1e30f; l_run[u] = 0.f;
        o2[u][0] = 0ull; o2[u][1] = 0ull;
    }

    for (int jt = 0; jt <= it; jt++) {
        const int j0 = jt * 64;
        __syncthreads();

        // stage K (swizzled) + V
#pragma unroll
        for (int p = 0; p < 8; p++) {
            int idx = p * 128 + tid;
            int j = idx >> 4, k4 = idx & 15;
            const float* base = qkv + ((size_t)(j0 + j) * BB + b) * 1536 + n * 64;
            *(float4*)(Ks + j * 64 + 4 * (k4 ^ (j >> 2))) =
                *(const float4*)(base + 512 + 4 * k4);
            *(float4*)(Vs + j * 68 + 4 * k4) = *(const float4*)(base + 1024 + 4 * k4);
        }
        // stage R band, dd = 0..126 (swizzled)
        const int m_base = j0 - i0 + 1984;
        for (int idx = tid; idx < 127 * 16; idx += 128) {
            int dd = idx >> 4, k4 = idx & 15;
            int gm = m_base + dd;
            float4 rv = make_float4(0.f, 0.f, 0.f, 0.f);
            if (gm < TT)
                rv = *(const float4*)(rbuf + (size_t)gm * 512 + n * 64 + 4 * k4);
            *(float4*)(Rs + dd * 64 + 4 * (k4 ^ ((dd >> 2) & 15))) = rv;
        }
        __syncthreads();

        // corr[dd] = delta · r_dd
        if (tid < 127) {
            const float4* rrow = (const float4*)(Rs + tid * 64);
            int key = (tid >> 2) & 15;
            float s = 0.f;
#pragma unroll
            for (int k4 = 0; k4 < 16; k4++) {
                float4 rv = rrow[k4 ^ key];
                float4 dl = ((const float4*)delta)[k4];
                s = fmaf(dl.x, rv.x, s); s = fmaf(dl.y, rv.y, s);
                s = fmaf(dl.z, rv.z, s); s = fmaf(dl.w, rv.w, s);
            }
            corr[tid] = s;
        }
        __syncthreads();

        // ---- score: 8x4 micro, k-packed ----
        u64 s2[8][4];
#pragma unroll
        for (int u = 0; u < 8; u++)
#pragma unroll
            for (int v = 0; v < 4; v++) s2[u][v] = 0ull;

        const float* qb = qws + 8 * ty * 64;
        const float* kb = Ks + 4 * tx * 64;

#pragma unroll 2
        for (int k4 = 0; k4 < 16; k4++) {
            ulonglong2 qv[8];
#pragma unroll
            for (int u = 0; u < 8; u++)
                qv[u] = *(const ulonglong2*)(qb + u * 64 + 4 * k4);
            int sk = 4 * (k4 ^ tx);
#pragma unroll
            for (int v = 0; v < 4; v++) {
                ulonglong2 kv = *(const ulonglong2*)(kb + v * 64 + sk);
#pragma unroll
                for (int u = 0; u < 8; u++) {
                    s2[u][v] = ffma2(qv[u].x, kv.x, s2[u][v]);
                    s2[u][v] = ffma2(qv[u].y, kv.y, s2[u][v]);
                }
            }
#pragma unroll
            for (int t = 0; t < 11; t++) {
                int row = rbase + t;
                ulonglong2 rv = *(const ulonglong2*)(Rs + row * 64 + 4 * (k4 ^ ((row >> 2) & 15)));
#pragma unroll
                for (int u = 0; u < 8; u++) {
                    int v = u + t - 7;
                    if (v >= 0 && v < 4) {
                        s2[u][v] = ffma2(qv[u].x, rv.x, s2[u][v]);
                        s2[u][v] = ffma2(qv[u].y, rv.y, s2[u][v]);
                    }
                }
            }
        }

        // ---- epilogue + online softmax ----
#pragma unroll
        for (int u = 0; u < 8; u++) {
            float sv[4];
#pragma unroll
            for (int v = 0; v < 4; v++) {
                float lo, hi; upk2(s2[u][v], lo, hi);
                float s = (lo + hi + corr[rbase + v - u + 7]) * 0.125f;
                if (j0 + 4 * tx + v > i0 + 8 * ty + u) s = -1e30f;
                sv[v] = s;
            }
            float mloc = fmaxf(fmaxf(sv[0], sv[1]), fmaxf(sv[2], sv[3]));
#pragma unroll
            for (int off = 1; off < 16; off <<= 1)
                mloc = fmaxf(mloc, __shfl_xor_sync(0xffffffffu, mloc, off));
            float m_new = fmaxf(m_run[u], mloc);
            float scl = __expf(m_run[u] - m_new);
            m_run[u] = m_new;
            float ls = 0.f;
#pragma unroll
            for (int v = 0; v < 4; v++) {
                float p = __expf(sv[v] - m_new);
                sv[v] = p;
                ls += p;
            }
#pragma unroll
            for (int off = 1; off < 16; off <<= 1)
                ls += __shfl_xor_sync(0xffffffffu, ls, off);
            l_run[u] = l_run[u] * scl + ls;
            u64 sc2 = splat2(scl);
            o2[u][0] = fmul2(o2[u][0], sc2);
            o2[u][1] = fmul2(o2[u][1], sc2);
            *(float4*)&Ps[(8 * ty + u) * 68 + 4 * tx] =
                make_float4(sv[0], sv[1], sv[2], sv[3]);
        }
        __syncthreads();

        // ---- PV ----
#pragma unroll 4
        for (int j = 0; j < 64; j++) {
            float4 v4 = *(const float4*)&Vs[j * 68 + 4 * tx];
            u64 vv0 = pk2(v4.x, v4.y), vv1 = pk2(v4.z, v4.w);
#pragma unroll
            for (int u = 0; u < 8; u++) {
                u64 ps = splat2(Ps[(8 * ty + u) * 68 + j]);
                o2[u][0] = ffma2(ps, vv0, o2[u][0]);
                o2[u][1] = ffma2(ps, vv1, o2[u][1]);
            }
        }
    }

    // ---- normalize + write ----
#pragma unroll
    for (int u = 0; u < 8; u++) {
        float inv = 1.f / l_run[u];
        int i = i0 + 8 * ty + u;
        float a0, a1, a2, a3;
        upk2(o2[u][0], a0, a1);
        upk2(o2[u][1], a2, a3);
        *(float4*)&att[((size_t)i * BB + b) * 512 + n * 64 + 4 * tx] =
            make_float4(a0 * inv, a1 * inv, a2 * inv, a3 * inv);
    }
}

// ---------------------------------------------------------------------------
extern "C" void kernel_launch(void* const* d_in, const int* in_sizes, int n_in,
                              void* d_out, int out_size) {
    const float* input = (const float*)d_in[0];
    const float* pos   = (const float*)d_in[1];
    const float* mu    = (const float*)d_in[3];
    const float* rho   = (const float*)d_in[4];
    const float* eps   = (const float*)d_in[5];
    float* out = (float*)d_out;

    float *w, *qkv, *r, *att;
    cudaGetSymbolAddress((void**)&w,   g_w);
    cudaGetSymbolAddress((void**)&qkv, g_qkv);
    cudaGetSymbolAddress((void**)&r,   g_r);
    cudaGetSymbolAddress((void**)&att, g_att);

    static bool attr_set = false;
    if (!attr_set) {
        cudaFuncSetAttribute(k_flash, cudaFuncAttributeMaxDynamicSharedMemorySize,
                             SMF * (int)sizeof(float));
        attr_set = true;
    }

    k_sample_w<<<(N_W + 255) / 256, 256>>>(mu, rho, eps, w, N_W);

    k_gemm<<<dim3(1536 / 128, 4096 / 128), 256>>>(input, w + OFF_INW, w + OFF_INB,
                                                  qkv, TT * BB, 3 * DD, DD);
    k_gemm<<<dim3(512 / 128, 2048 / 128), 256>>>(pos, w + OFF_POSW, w + OFF_POSB,
                                                 r, TT, DD, DD);
    k_flash<<<dim3(BB * NHH, 32), 128, SMF * sizeof(float)>>>(qkv, r, w, att);

    k_gemm<<<dim3(512 / 128, 4096 / 128), 256>>>(att, w + OFF_OUTW, w + OFF_OUTB,
                                                 out, TT * BB, DD, DD);
}

// round 7
// speedup vs baseline: 1.0022x; 1.0022x over previous
#include <cuda_runtime.h>
#include <math.h>

#define TT  2048
#define BB  2
#define DD  512
#define NHH 8

#define OFF_INW   0
#define OFF_OUTW  786432
#define OFF_POSW  1048576
#define OFF_INB   1310720
#define OFF_OUTB  1312256
#define OFF_POSB  1312768
#define OFF_RWB   1313280
#define OFF_RRB   1313792
#define N_W       1314304

typedef unsigned long long u64;

__device__ __forceinline__ void upk2(u64 v, float& lo, float& hi) {
    asm("mov.b64 {%0, %1}, %2;" : "=f"(lo), "=f"(hi) : "l"(v));
}
__device__ __forceinline__ u64 ffma2(u64 a, u64 b, u64 c) {
    u64 d; asm("fma.rn.f32x2 %0, %1, %2, %3;" : "=l"(d) : "l"(a), "l"(b), "l"(c));
    return d;
}
__device__ __forceinline__ u64 fmul2(u64 a, u64 b) {
    u64 d; asm("mul.rn.f32x2 %0, %1, %2;" : "=l"(d) : "l"(a), "l"(b)); return d;
}
__device__ __forceinline__ u64 splat2(float x) {
    u64 r; asm("mov.b64 %0, {%1, %1};" : "=l"(r) : "f"(x)); return r;
}
__device__ __forceinline__ u64 pk2(float lo, float hi) {
    u64 r; asm("mov.b64 %0, {%1, %2};" : "=l"(r) : "f"(lo), "f"(hi)); return r;
}

__device__ float g_w[N_W];
__device__ float g_qkv[(size_t)TT * BB * 3 * DD];
__device__ float g_r[(size_t)TT * DD];
__device__ float g_att[(size_t)TT * BB * DD];

// ---------------------------------------------------------------------------
__global__ void k_sample_w(const float* __restrict__ mu,
                           const float* __restrict__ rho,
                           const float* __restrict__ eps,
                           float* __restrict__ w, int n) {
    int i = blockIdx.x * blockDim.x + threadIdx.x;
    if (i < n) {
        float r = rho[i];
        float sp = (r > 20.f) ? r : log1pf(expf(r));
        w[i] = fmaf(sp, eps[i], mu[i]);
    }
}

// ---------------------------------------------------------------------------
// GEMM: C[M,N] = A[M,K] @ W[N,K]^T + bias. 128x128 tile, 8x8 micro,
// j-packed FFMA2 (BsT transposed in smem). M,N %128==0, K %32==0.
// ---------------------------------------------------------------------------
__global__ __launch_bounds__(256, 2)
void k_gemm(const float* __restrict__ A, const float* __restrict__ W,
            const float* __restrict__ bias, float* __restrict__ C,
            int M, int N, int K) {
    __shared__ float As[128 * 32];
    __shared__ float BsT[32 * 132];
    const int tid = threadIdx.x, tx = tid & 15, ty = tid >> 4;
    const int m0 = blockIdx.y * 128, n0 = blockIdx.x * 128;

    u64 acc[8][4];
#pragma unroll
    for (int u = 0; u < 8; u++)
#pragma unroll
        for (int p = 0; p < 4; p++) acc[u][p] = 0ull;

    for (int k0 = 0; k0 < K; k0 += 32) {
        __syncthreads();
#pragma unroll
        for (int p = 0; p < 4; p++) {
            int idx = p * 256 + tid;
            int mi = idx >> 3, k4 = idx & 7;
            *(float4*)(As + mi * 32 + 4 * k4) =
                *(const float4*)(A + (size_t)(m0 + mi) * K + k0 + 4 * k4);
            float4 wv = *(const float4*)(W + (size_t)(n0 + mi) * K + k0 + 4 * k4);
            BsT[(4 * k4 + 0) * 132 + mi] = wv.x;
            BsT[(4 * k4 + 1) * 132 + mi] = wv.y;
            BsT[(4 * k4 + 2) * 132 + mi] = wv.z;
            BsT[(4 * k4 + 3) * 132 + mi] = wv.w;
        }
        __syncthreads();
#pragma unroll 2
        for (int k4 = 0; k4 < 8; k4++) {
            float4 av[8];
#pragma unroll
            for (int u = 0; u < 8; u++)
                av[u] = *(const float4*)(As + (8 * ty + u) * 32 + 4 * k4);
#pragma unroll
            for (int kk = 0; kk < 4; kk++) {
                const float* bp = BsT + (4 * k4 + kk) * 132;
                ulonglong2 b0 = *(const ulonglong2*)(bp + 4 * tx);
                ulonglong2 b1 = *(const ulonglong2*)(bp + 64 + 4 * tx);
#pragma unroll
                for (int u = 0; u < 8; u++) {
                    u64 as = splat2(((const float*)&av[u])[kk]);
                    acc[u][0] = ffma2(as, b0.x, acc[u][0]);
                    acc[u][1] = ffma2(as, b0.y, acc[u][1]);
                    acc[u][2] = ffma2(as, b1.x, acc[u][2]);
                    acc[u][3] = ffma2(as, b1.y, acc[u][3]);
                }
            }
        }
    }

    float4 ba = *(const float4*)(bias + n0 + 4 * tx);
    float4 bb = *(const float4*)(bias + n0 + 64 + 4 * tx);
#pragma unroll
    for (int u = 0; u < 8; u++) {
        int m = m0 + 8 * ty + u;
        float c0, c1, c2, c3, c4, c5, c6, c7;
        upk2(acc[u][0], c0, c1); upk2(acc[u][1], c2, c3);
        upk2(acc[u][2], c4, c5); upk2(acc[u][3], c6, c7);
        *(float4*)(C + (size_t)m * N + n0 + 4 * tx) =
            make_float4(c0 + ba.x, c1 + ba.y, c2 + ba.z, c3 + ba.w);
        *(float4*)(C + (size_t)m * N + n0 + 64 + 4 * tx) =
            make_float4(c4 + bb.x, c5 + bb.y, c6 + bb.z, c7 + bb.w);
    }
}

// ---------------------------------------------------------------------------
// Flash attention, fused rel-shift. 64x64 tile, 128 threads, 8(i)x4(j) micro,
// k-packed FFMA2. score = 0.125*(qw·k + qw·r_dd + corr[dd]),
// dd = j-i+63 (tile-rel), corr = delta·r_dd, delta = rrb - rwb.
// ---------------------------------------------------------------------------
#define SMF 25216   // floats (100864 bytes)

__global__ __launch_bounds__(128, 2)
void k_flash(const float* __restrict__ qkv, const float* __restrict__ rbuf,
             const float* __restrict__ w, float* __restrict__ att) {
    const int combo = blockIdx.x, b = combo >> 3, n = combo & 7;
    const int it = 31 - (int)blockIdx.y;
    const int i0 = it * 64;
    const int tid = threadIdx.x, tx = tid & 15, ty = tid >> 4;   // ty 0..7

    extern __shared__ float sm[];
    float* qws = sm;             // [64][64] rows i, k-contig
    float* Ks  = sm + 4096;      // [64][64] swizzled, key j>>2
    float* Vs  = sm + 8192;      // [64][68]
    float* Ps  = sm + 12544;     // [64][68]
    float* Rs  = sm + 16896;     // [127][64] swizzled, key (dd>>2)&15
    float* delta = sm + 25024;   // [64]
    float* corr  = sm + 25088;   // [128]

    if (tid < 64)
        delta[tid] = w[OFF_RRB + n * 64 + tid] - w[OFF_RWB + n * 64 + tid];

#pragma unroll
    for (int p = 0; p < 8; p++) {
        int idx = p * 128 + tid;
        int i = idx >> 4, k4 = idx & 15;
        float4 qv = *(const float4*)(qkv + ((size_t)(i0 + i) * BB + b) * 1536 + n * 64 + 4 * k4);
        float4 bw = *(const float4*)(w + OFF_RWB + n * 64 + 4 * k4);
        *(float4*)(qws + i * 64 + 4 * k4) =
            make_float4(qv.x + bw.x, qv.y + bw.y, qv.z + bw.z, qv.w + bw.w);
    }

    const int rbase = 4 * tx - 8 * ty + 56;    // dd row at t=0 (>=0)
    float m_run[8], l_run[8];
    u64 o2[8][2];
#pragma unroll
    for (int u = 0; u < 8; u++) {
        m_run[u] = -1e30f; l_run[u] = 0.f;
        o2[u][0] = 0ull; o2[u][1] = 0ull;
    }

    for (int jt = 0; jt <= it; jt++) {
        const int j0 = jt * 64;
        __syncthreads();

        // stage K (swizzled) + V
#pragma unroll
        for (int p = 0; p < 8; p++) {
            int idx = p * 128 + tid;
            int j = idx >> 4, k4 = idx & 15;
            const float* base = qkv + ((size_t)(j0 + j) * BB + b) * 1536 + n * 64;
            *(float4*)(Ks + j * 64 + 4 * (k4 ^ (j >> 2))) =
                *(const float4*)(base + 512 + 4 * k4);
            *(float4*)(Vs + j * 68 + 4 * k4) = *(const float4*)(base + 1024 + 4 * k4);
        }
        // stage R band, dd = 0..126 (swizzled)
        const int m_base = j0 - i0 + 1984;
        for (int idx = tid; idx < 127 * 16; idx += 128) {
            int dd = idx >> 4, k4 = idx & 15;
            int gm = m_base + dd;
            float4 rv = make_float4(0.f, 0.f, 0.f, 0.f);
            if (gm < TT)
                rv = *(const float4*)(rbuf + (size_t)gm * 512 + n * 64 + 4 * k4);
            *(float4*)(Rs + dd * 64 + 4 * (k4 ^ ((dd >> 2) & 15))) = rv;
        }
        __syncthreads();

        // corr[dd] = delta · r_dd
        if (tid < 127) {
            const float4* rrow = (const float4*)(Rs + tid * 64);
            int key = (tid >> 2) & 15;
            float s = 0.f;
#pragma unroll
            for (int k4 = 0; k4 < 16; k4++) {
                float4 rv = rrow[k4 ^ key];
                float4 dl = ((const float4*)delta)[k4];
                s = fmaf(dl.x, rv.x, s); s = fmaf(dl.y, rv.y, s);
                s = fmaf(dl.z, rv.z, s); s = fmaf(dl.w, rv.w, s);
            }
            corr[tid] = s;
        }
        __syncthreads();

        // ---- score: 8x4 micro, k-packed ----
        u64 s2[8][4];
#pragma unroll
        for (int u = 0; u < 8; u++)
#pragma unroll
            for (int v = 0; v < 4; v++) s2[u][v] = 0ull;

        const float* qb = qws + 8 * ty * 64;
        const float* kb = Ks + 4 * tx * 64;

#pragma unroll 2
        for (int k4 = 0; k4 < 16; k4++) {
            ulonglong2 qv[8];
#pragma unroll
            for (int u = 0; u < 8; u++)
                qv[u] = *(const ulonglong2*)(qb + u * 64 + 4 * k4);
            int sk = 4 * (k4 ^ tx);
#pragma unroll
            for (int v = 0; v < 4; v++) {
                ulonglong2 kv = *(const ulonglong2*)(kb + v * 64 + sk);
#pragma unroll
                for (int u = 0; u < 8; u++) {
                    s2[u][v] = ffma2(qv[u].x, kv.x, s2[u][v]);
                    s2[u][v] = ffma2(qv[u].y, kv.y, s2[u][v]);
                }
            }
#pragma unroll
            for (int t = 0; t < 11; t++) {
                int row = rbase + t;
                ulonglong2 rv = *(const ulonglong2*)(Rs + row * 64 + 4 * (k4 ^ ((row >> 2) & 15)));
#pragma unroll
                for (int u = 0; u < 8; u++) {
                    int v = u + t - 7;
                    if (v >= 0 && v < 4) {
                        s2[u][v] = ffma2(qv[u].x, rv.x, s2[u][v]);
                        s2[u][v] = ffma2(qv[u].y, rv.y, s2[u][v]);
                    }
                }
            }
        }

        // ---- epilogue + online softmax ----
#pragma unroll
        for (int u = 0; u < 8; u++) {
            float sv[4];
#pragma unroll
            for (int v = 0; v < 4; v++) {
                float lo, hi; upk2(s2[u][v], lo, hi);
                float s = (lo + hi + corr[rbase + v - u + 7]) * 0.125f;
                if (j0 + 4 * tx + v > i0 + 8 * ty + u) s = -1e30f;
                sv[v] = s;
            }
            float mloc = fmaxf(fmaxf(sv[0], sv[1]), fmaxf(sv[2], sv[3]));
#pragma unroll
            for (int off = 1; off < 16; off <<= 1)
                mloc = fmaxf(mloc, __shfl_xor_sync(0xffffffffu, mloc, off));
            float m_new = fmaxf(m_run[u], mloc);
            float scl = __expf(m_run[u] - m_new);
            m_run[u] = m_new;
            float ls = 0.f;
#pragma unroll
            for (int v = 0; v < 4; v++) {
                float p = __expf(sv[v] - m_new);
                sv[v] = p;
                ls += p;
            }
#pragma unroll
            for (int off = 1; off < 16; off <<= 1)
                ls += __shfl_xor_sync(0xffffffffu, ls, off);
            l_run[u] = l_run[u] * scl + ls;
            u64 sc2 = splat2(scl);
            o2[u][0] = fmul2(o2[u][0], sc2);
            o2[u][1] = fmul2(o2[u][1], sc2);
            *(float4*)&Ps[(8 * ty + u) * 68 + 4 * tx] =
                make_float4(sv[0], sv[1], sv[2], sv[3]);
        }
        __syncthreads();

        // ---- PV ----
#pragma unroll 4
        for (int j = 0; j < 64; j++) {
            float4 v4 = *(const float4*)&Vs[j * 68 + 4 * tx];
            u64 vv0 = pk2(v4.x, v4.y), vv1 = pk2(v4.z, v4.w);
#pragma unroll
            for (int u = 0; u < 8; u++) {
                u64 ps = splat2(Ps[(8 * ty + u) * 68 + j]);
                o2[u][0] = ffma2(ps, vv0, o2[u][0]);
                o2[u][1] = ffma2(ps, vv1, o2[u][1]);
            }
        }
    }

    // ---- normalize + write ----
#pragma unroll
    for (int u = 0; u < 8; u++) {
        float inv = 1.f / l_run[u];
        int i = i0 + 8 * ty + u;
        float a0, a1, a2, a3;
        upk2(o2[u][0], a0, a1);
        upk2(o2[u][1], a2, a3);
        *(float4*)&att[((size_t)i * BB + b) * 512 + n * 64 + 4 * tx] =
            make_float4(a0 * inv, a1 * inv, a2 * inv, a3 * inv);
    }
}

// ---------------------------------------------------------------------------
extern "C" void kernel_launch(void* const* d_in, const int* in_sizes, int n_in,
                              void* d_out, int out_size) {
    const float* input = (const float*)d_in[0];
    const float* pos   = (const float*)d_in[1];
    const float* mu    = (const float*)d_in[3];
    const float* rho   = (const float*)d_in[4];
    const float* eps   = (const float*)d_in[5];
    float* out = (float*)d_out;

    float *w, *qkv, *r, *att;
    cudaGetSymbolAddress((void**)&w,   g_w);
    cudaGetSymbolAddress((void**)&qkv, g_qkv);
    cudaGetSymbolAddress((void**)&r,   g_r);
    cudaGetSymbolAddress((void**)&att, g_att);

    static bool attr_set = false;
    if (!attr_set) {
        cudaFuncSetAttribute(k_flash, cudaFuncAttributeMaxDynamicSharedMemorySize,
                             SMF * (int)sizeof(float));
        attr_set = true;
    }

    k_sample_w<<<(N_W + 255) / 256, 256>>>(mu, rho, eps, w, N_W);

    k_gemm<<<dim3(1536 / 128, 4096 / 128), 256>>>(input, w + OFF_INW, w + OFF_INB,
                                                  qkv, TT * BB, 3 * DD, DD);
    k_gemm<<<dim3(512 / 128, 2048 / 128), 256>>>(pos, w + OFF_POSW, w + OFF_POSB,
                                                 r, TT, DD, DD);
    k_flash<<<dim3(BB * NHH, 32), 128, SMF * sizeof(float)>>>(qkv, r, w, att);

    k_gemm<<<dim3(512 / 128, 4096 / 128), 256>>>(att, w + OFF_OUTW, w + OFF_OUTB,
                                                 out, TT * BB, DD, DD);
}

// round 10
// speedup vs baseline: 1.3293x; 1.3263x over previous
#include <cuda_runtime.h>
#include <cuda_bf16.h>
#include <cstdint>
#include <math.h>

#define TT  2048
#define BB  2
#define DD  512
#define NHH 8

#define OFF_INW   0
#define OFF_OUTW  786432
#define OFF_POSW  1048576
#define OFF_INB   1310720
#define OFF_OUTB  1312256
#define OFF_POSB  1312768
#define OFF_RWB   1313280
#define OFF_RRB   1313792
#define N_W       1314304

typedef unsigned long long u64;
typedef unsigned int u32;

__device__ __forceinline__ void upk2(u64 v, float& lo, float& hi) {
    asm("mov.b64 {%0, %1}, %2;" : "=f"(lo), "=f"(hi) : "l"(v));
}
__device__ __forceinline__ u64 ffma2(u64 a, u64 b, u64 c) {
    u64 d; asm("fma.rn.f32x2 %0, %1, %2, %3;" : "=l"(d) : "l"(a), "l"(b), "l"(c));
    return d;
}
__device__ __forceinline__ u64 fmul2(u64 a, u64 b) {
    u64 d; asm("mul.rn.f32x2 %0, %1, %2;" : "=l"(d) : "l"(a), "l"(b)); return d;
}
__device__ __forceinline__ u64 splat2(float x) {
    u64 r; asm("mov.b64 %0, {%1, %1};" : "=l"(r) : "f"(x)); return r;
}
__device__ __forceinline__ u64 pk2(float lo, float hi) {
    u64 r; asm("mov.b64 %0, {%1, %2};" : "=l"(r) : "f"(lo), "f"(hi)); return r;
}
__device__ __forceinline__ u32 s2u(const void* p) {
    u32 a;
    asm("{.reg .u64 t; cvta.to.shared.u64 t, %1; cvt.u32.u64 %0, t;}" : "=r"(a) : "l"(p));
    return a;
}
__device__ __forceinline__ void ldm4(u32* r, u32 addr) {
    asm volatile("ldmatrix.sync.aligned.m8n8.x4.shared.b16 {%0,%1,%2,%3}, [%4];"
        : "=r"(r[0]), "=r"(r[1]), "=r"(r[2]), "=r"(r[3]) : "r"(addr));
}
__device__ __forceinline__ void mma_bf16(float* c, const u32* a, u32 b0, u32 b1) {
    asm volatile("mma.sync.aligned.m16n8k16.row.col.f32.bf16.bf16.f32 "
        "{%0,%1,%2,%3}, {%4,%5,%6,%7}, {%8,%9}, {%0,%1,%2,%3};"
        : "+f"(c[0]), "+f"(c[1]), "+f"(c[2]), "+f"(c[3])
        : "r"(a[0]), "r"(a[1]), "r"(a[2]), "r"(a[3]), "r"(b0), "r"(b1));
}
__device__ __forceinline__ u32 swz(u32 b) { return b ^ ((b >> 3) & 0x70); }

__device__ float g_w[N_W];
__device__ float g_qkv[(size_t)TT * BB * 3 * DD];
__device__ float g_r[(size_t)TT * DD];
__device__ float g_att[(size_t)TT * BB * DD];
__device__ __nv_bfloat16 g_ah[2097152], g_al[2097152];
__device__ __nv_bfloat16 g_wh[1310720], g_wl[1310720];

// ---------------------------------------------------------------------------
__global__ void k_sample_w(const float* __restrict__ mu, const float* __restrict__ rho,
                           const float* __restrict__ eps, float* __restrict__ w, int n) {
    int i = blockIdx.x * blockDim.x + threadIdx.x;
    if (i < n) {
        float r = rho[i];
        float sp = (r > 20.f) ? r : log1pf(expf(r));
        w[i] = fmaf(sp, eps[i], mu[i]);
    }
}

__global__ void k_split(const float* __restrict__ x, __nv_bfloat16* __restrict__ hi,
                        __nv_bfloat16* __restrict__ lo, int n) {
    int i = blockIdx.x * blockDim.x + threadIdx.x;
    if (i < n) {
        float v = x[i];
        __nv_bfloat16 h = __float2bfloat16(v);
        hi[i] = h;
        lo[i] = __float2bfloat16(v - __bfloat162float(h));
    }
}

// ---------------------------------------------------------------------------
// HMMA GEMM: C[M,N] = A[M,512] @ W[N,512]^T + bias, bf16 hi/lo 3-pass.
// 128x128 CTA tile, 8 warps (2M x 4N), K chunks of 64, SW128 smem, ldmatrix.
// ---------------------------------------------------------------------------
#define GS_AH 0
#define GS_AL 16384
#define GS_BH 32768
#define GS_BL 49152
#define SMEM_G 65536

__global__ __launch_bounds__(256, 2)
void k_hgemm(const __nv_bfloat16* __restrict__ Ah, const __nv_bfloat16* __restrict__ Al,
             const __nv_bfloat16* __restrict__ Wh, const __nv_bfloat16* __restrict__ Wl,
             const float* __restrict__ bias, float* __restrict__ C, int M, int N) {
    extern __shared__ char smem[];
    const u32 sb = s2u(smem);
    const int tid = threadIdx.x, lane = tid & 31, warp = tid >> 5;
    const int m0 = blockIdx.y * 128, n0 = blockIdx.x * 128;
    const int wm = (warp >> 2) * 64, wn = (warp & 3) * 32;

    // lane->row/col for ldmatrix address supply
    const int rA = (lane & 7) + ((lane >> 3) & 1) * 8;   // A: g0,g1 rows; g2,g3 col+16
    const int cA = ((lane >> 4) & 1) * 16;
    const int rB = (lane & 7) + ((lane >> 4) & 1) * 8;   // B: g0,g1 cols; g2,g3 rows+8
    const int cB = ((lane >> 3) & 1) * 16;

    float acc[4][4][4];
#pragma unroll
    for (int u = 0; u < 4; u++)
#pragma unroll
        for (int t = 0; t < 4; t++)
#pragma unroll
            for (int e = 0; e < 4; e++) acc[u][t][e] = 0.f;

    for (int c = 0; c < 8; c++) {
        __syncthreads();
        // stage A/W hi+lo: rows x 64 bf16 (128B) swizzled
#pragma unroll
        for (int p = 0; p < 4; p++) {
            int idx = p * 256 + tid;
            int row = idx >> 3, c8 = idx & 7;
            u32 off = swz(row * 128 + c8 * 16);
            size_t ga = (size_t)(m0 + row) * 512 + c * 64 + c8 * 8;
            size_t gb = (size_t)(n0 + row) * 512 + c * 64 + c8 * 8;
            *(uint4*)(smem + GS_AH + off) = *(const uint4*)(Ah + ga);
            *(uint4*)(smem + GS_AL + off) = *(const uint4*)(Al + ga);
            *(uint4*)(smem + GS_BH + off) = *(const uint4*)(Wh + gb);
            *(uint4*)(smem + GS_BL + off) = *(const uint4*)(Wl + gb);
        }
        __syncthreads();

#pragma unroll
        for (int s = 0; s < 4; s++) {
            u32 ah[4][4], al[4][4];
#pragma unroll
            for (int u = 0; u < 4; u++) {
                u32 off = swz((wm + u * 16 + rA) * 128 + cA + s * 32);
                ldm4(ah[u], sb + GS_AH + off);
                ldm4(al[u], sb + GS_AL + off);
            }
#pragma unroll
            for (int t = 0; t < 2; t++) {
                u32 bh[4], bl[4];
                u32 off = swz((wn + t * 16 + rB) * 128 + cB + s * 32);
                ldm4(bh, sb + GS_BH + off);
                ldm4(bl, sb + GS_BL + off);
#pragma unroll
                for (int h = 0; h < 2; h++) {
                    int n8 = t * 2 + h;
#pragma unroll
                    for (int u = 0; u < 4; u++) {
                        mma_bf16(acc[u][n8], ah[u], bh[2 * h], bh[2 * h + 1]);
                        mma_bf16(acc[u][n8], ah[u], bl[2 * h], bl[2 * h + 1]);
                        mma_bf16(acc[u][n8], al[u], bh[2 * h], bh[2 * h + 1]);
                    }
                }
            }
        }
    }

    // epilogue: c0,c1 -> (row, col..col+1); c2,c3 -> (row+8, ...)
#pragma unroll
    for (int u = 0; u < 4; u++) {
#pragma unroll
        for (int n8 = 0; n8 < 4; n8++) {
            int col = n0 + wn + n8 * 8 + 2 * (lane & 3);
            int row = m0 + wm + u * 16 + (lane >> 2);
            float2 bv = *(const float2*)(bias + col);
            *(float2*)(C + (size_t)row * N + col) =
                make_float2(acc[u][n8][0] + bv.x, acc[u][n8][1] + bv.y);
            *(float2*)(C + (size_t)(row + 8) * N + col) =
                make_float2(acc[u][n8][2] + bv.x, acc[u][n8][3] + bv.y);
        }
    }
}

// ---------------------------------------------------------------------------
// Flash attention (round-5 proven). 64x64 tiles, 256 thr, 4x4 micro, k-packed.
// ---------------------------------------------------------------------------
#define SMF 25216

__global__ __launch_bounds__(256, 2)
void k_flash(const float* __restrict__ qkv, const float* __restrict__ rbuf,
             const float* __restrict__ w, float* __restrict__ att) {
    const int combo = blockIdx.x, b = combo >> 3, n = combo & 7;
    const int it = (int)gridDim.y - 1 - (int)blockIdx.y;
    const int i0 = it * 64;
    const int tid = threadIdx.x, tx = tid & 15, ty = tid >> 4;

    extern __shared__ float sm[];
    float* qws = sm;
    float* Ks  = sm + 4096;
    float* Vs  = sm + 8192;
    float* Ps  = sm + 12544;
    float* Rs  = sm + 16896;
    float* delta = sm + 25024;
    float* corr  = sm + 25088;

    if (tid < 64)
        delta[tid] = w[OFF_RRB + n * 64 + tid] - w[OFF_RWB + n * 64 + tid];

#pragma unroll
    for (int p = 0; p < 4; p++) {
        int idx = p * 256 + tid;
        int i = idx >> 4, k4 = idx & 15;
        float4 qv = *(const float4*)(qkv + ((size_t)(i0 + i) * BB + b) * 1536 + n * 64 + 4 * k4);
        float4 bw = *(const float4*)(w + OFF_RWB + n * 64 + 4 * k4);
        *(float4*)(qws + i * 64 + 4 * k4) =
            make_float4(qv.x + bw.x, qv.y + bw.y, qv.z + bw.z, qv.w + bw.w);
    }

    const int ddbase = 4 * (tx - ty) + 60;
    float m_run[4], l_run[4];
    u64 o2[4][2];
#pragma unroll
    for (int u = 0; u < 4; u++) {
        m_run[u] = -1e30f; l_run[u] = 0.f;
        o2[u][0] = 0ull; o2[u][1] = 0ull;
    }

    for (int jt = 0; jt <= it; jt++) {
        const int j0 = jt * 64;
        __syncthreads();
#pragma unroll
        for (int p = 0; p < 4; p++) {
            int idx = p * 256 + tid;
            int j = idx >> 4, k4 = idx & 15;
            const float* base = qkv + ((size_t)(j0 + j) * BB + b) * 1536 + n * 64;
            *(float4*)(Ks + j * 64 + 4 * (k4 ^ (j >> 2))) = *(const float4*)(base + 512 + 4 * k4);
            *(float4*)(Vs + j * 68 + 4 * k4) = *(const float4*)(base + 1024 + 4 * k4);
        }
        const int m_base = j0 - i0 + 1984;
        for (int idx = tid; idx < 127 * 16; idx += 256) {
            int dd = idx >> 4, k4 = idx & 15;
            int gm = m_base + dd;
            float4 rv = make_float4(0.f, 0.f, 0.f, 0.f);
            if (gm < TT) rv = *(const float4*)(rbuf + (size_t)gm * 512 + n * 64 + 4 * k4);
            *(float4*)(Rs + dd * 64 + 4 * (k4 ^ ((dd >> 2) & 15))) = rv;
        }
        __syncthreads();

        if (tid < 127) {
            const float4* rrow = (const float4*)(Rs + tid * 64);
            int key = (tid >> 2) & 15;
            float s = 0.f;
#pragma unroll
            for (int k4 = 0; k4 < 16; k4++) {
                float4 rv = rrow[k4 ^ key];
                float4 dl = ((const float4*)delta)[k4];
                s = fmaf(dl.x, rv.x, s); s = fmaf(dl.y, rv.y, s);
                s = fmaf(dl.z, rv.z, s); s = fmaf(dl.w, rv.w, s);
            }
            corr[tid] = s;
        }
        __syncthreads();

        u64 s2[4][4];
#pragma unroll
        for (int u = 0; u < 4; u++)
#pragma unroll
            for (int v = 0; v < 4; v++) s2[u][v] = 0ull;

        const float* qb = qws + 4 * ty * 64;
        const float* kb = Ks + 4 * tx * 64;
        const float* rb = Rs + ddbase * 64;
        const int keyA = (ddbase >> 2) & 15;
        const int keyB = ((ddbase >> 2) + 1) & 15;

#pragma unroll 4
        for (int k4 = 0; k4 < 16; k4++) {
            ulonglong2 qv[4], kv[4];
#pragma unroll
            for (int u = 0; u < 4; u++)
                qv[u] = *(const ulonglong2*)(qb + u * 64 + 4 * k4);
            int sk = 4 * (k4 ^ tx);
#pragma unroll
            for (int v = 0; v < 4; v++)
                kv[v] = *(const ulonglong2*)(kb + v * 64 + sk);
#pragma unroll
            for (int u = 0; u < 4; u++)
#pragma unroll
                for (int v = 0; v < 4; v++) {
                    s2[u][v] = ffma2(qv[u].x, kv[v].x, s2[u][v]);
                    s2[u][v] = ffma2(qv[u].y, kv[v].y, s2[u][v]);
                }
            int sA = 4 * (k4 ^ keyA), sB = 4 * (k4 ^ keyB);
#pragma unroll
            for (int t = 0; t < 7; t++) {
                ulonglong2 rv = *(const ulonglong2*)(rb + t * 64 + (t < 4 ? sA : sB));
#pragma unroll
                for (int u = 0; u < 4; u++) {
                    int v = u + t - 3;
                    if (v >= 0 && v < 4) {
                        s2[u][v] = ffma2(qv[u].x, rv.x, s2[u][v]);
                        s2[u][v] = ffma2(qv[u].y, rv.y, s2[u][v]);
                    }
                }
            }
        }

        float sv[4][4];
#pragma unroll
        for (int u = 0; u < 4; u++)
#pragma unroll
            for (int v = 0; v < 4; v++) {
                float lo, hi; upk2(s2[u][v], lo, hi);
                float s = (lo + hi + corr[ddbase + 3 + v - u]) * 0.125f;
                if (j0 + 4 * tx + v > i0 + 4 * ty + u) s = -1e30f;
                sv[u][v] = s;
            }

#pragma unroll
        for (int u = 0; u < 4; u++) {
            float mloc = fmaxf(fmaxf(sv[u][0], sv[u][1]), fmaxf(sv[u][2], sv[u][3]));
#pragma unroll
            for (int off = 1; off < 16; off <<= 1)
                mloc = fmaxf(mloc, __shfl_xor_sync(0xffffffffu, mloc, off));
            float m_new = fmaxf(m_run[u], mloc);
            float scale = __expf(m_run[u] - m_new);
            m_run[u] = m_new;
            float ls = 0.f;
#pragma unroll
            for (int v = 0; v < 4; v++) {
                float p = __expf(sv[u][v] - m_new);
                sv[u][v] = p;
                ls += p;
            }
#pragma unroll
            for (int off = 1; off < 16; off <<= 1)
                ls += __shfl_xor_sync(0xffffffffu, ls, off);
            l_run[u] = l_run[u] * scale + ls;
            u64 sc2 = splat2(scale);
            o2[u][0] = fmul2(o2[u][0], sc2);
            o2[u][1] = fmul2(o2[u][1], sc2);
            *(float4*)&Ps[(4 * ty + u) * 68 + 4 * tx] =
                make_float4(sv[u][0], sv[u][1], sv[u][2], sv[u][3]);
        }
        __syncthreads();

#pragma unroll 4
        for (int j = 0; j < 64; j++) {
            float4 v4 = *(const float4*)&Vs[j * 68 + 4 * tx];
            u64 vv0 = pk2(v4.x, v4.y), vv1 = pk2(v4.z, v4.w);
#pragma unroll
            for (int u = 0; u < 4; u++) {
                u64 ps = splat2(Ps[(4 * ty + u) * 68 + j]);
                o2[u][0] = ffma2(ps, vv0, o2[u][0]);
                o2[u][1] = ffma2(ps, vv1, o2[u][1]);
            }
        }
    }

#pragma unroll
    for (int u = 0; u < 4; u++) {
        float inv = 1.f / l_run[u];
        int i = i0 + 4 * ty + u;
        float a0, a1, a2, a3;
        upk2(o2[u][0], a0, a1);
        upk2(o2[u][1], a2, a3);
        *(float4*)&att[((size_t)i * BB + b) * 512 + n * 64 + 4 * tx] =
            make_float4(a0 * inv, a1 * inv, a2 * inv, a3 * inv);
    }
}

// ---------------------------------------------------------------------------
extern "C" void kernel_launch(void* const* d_in, const int* in_sizes, int n_in,
                              void* d_out, int out_size) {
    const float* input = (const float*)d_in[0];
    const float* pos   = (const float*)d_in[1];
    const float* mu    = (const float*)d_in[3];
    const float* rho   = (const float*)d_in[4];
    const float* eps   = (const float*)d_in[5];
    float* out = (float*)d_out;

    float *w, *qkv, *r, *att;
    __nv_bfloat16 *ah, *al, *wh, *wl;
    cudaGetSymbolAddress((void**)&w,   g_w);
    cudaGetSymbolAddress((void**)&qkv, g_qkv);
    cudaGetSymbolAddress((void**)&r,   g_r);
    cudaGetSymbolAddress((void**)&att, g_att);
    cudaGetSymbolAddress((void**)&ah,  g_ah);
    cudaGetSymbolAddress((void**)&al,  g_al);
    cudaGetSymbolAddress((void**)&wh,  g_wh);
    cudaGetSymbolAddress((void**)&wl,  g_wl);

    static bool attr_set = false;
    if (!attr_set) {
        cudaFuncSetAttribute(k_flash, cudaFuncAttributeMaxDynamicSharedMemorySize,
                             SMF * (int)sizeof(float));
        cudaFuncSetAttribute(k_hgemm, cudaFuncAttributeMaxDynamicSharedMemorySize,
                             SMEM_G);
        attr_set = true;
    }

    k_sample_w<<<(N_W + 255) / 256, 256>>>(mu, rho, eps, w, N_W);
    k_split<<<(1310720 + 255) / 256, 256>>>(w, wh, wl, 1310720);

    // qkv = input @ in_w^T + in_b
    k_split<<<(2097152 + 255) / 256, 256>>>(input, ah, al, 2097152);
    k_hgemm<<<dim3(12, 32), 256, SMEM_G>>>(ah, al, wh + OFF_INW, wl + OFF_INW,
                                           w + OFF_INB, qkv, 4096, 1536);
    // r = pos @ pos_w^T + pos_b
    k_split<<<(1048576 + 255) / 256, 256>>>(pos, ah, al, 1048576);
    k_hgemm<<<dim3(4, 16), 256, SMEM_G>>>(ah, al, wh + OFF_POSW, wl + OFF_POSW,
                                          w + OFF_POSB, r, 2048, 512);
    // flash attention
    k_flash<<<dim3(BB * NHH, 32), 256, SMF * sizeof(float)>>>(qkv, r, w, att);

    // out = att @ out_w^T + out_b
    k_split<<<(2097152 + 255) / 256, 256>>>(att, ah, al, 2097152);
    k_hgemm<<<dim3(4, 32), 256, SMEM_G>>>(ah, al, wh + OFF_OUTW, wl + OFF_OUTW,
                                          w + OFF_OUTB, out, 4096, 512);
}

// round 11
// speedup vs baseline: 1.4861x; 1.1179x over previous
#include <cuda_runtime.h>
#include <cuda_bf16.h>
#include <cstdint>
#include <math.h>

#define TT  2048
#define BB  2
#define NHH 8

#define OFF_INW   0
#define OFF_OUTW  786432
#define OFF_POSW  1048576
#define OFF_INB   1310720
#define OFF_OUTB  1312256
#define OFF_POSB  1312768
#define OFF_RWB   1313280
#define OFF_RRB   1313792
#define N_W       1314304

typedef unsigned long long u64;
typedef unsigned int u32;

__device__ __forceinline__ u32 s2u(const void* p) {
    u32 a;
    asm("{.reg .u64 t; cvta.to.shared.u64 t, %1; cvt.u32.u64 %0, t;}" : "=r"(a) : "l"(p));
    return a;
}
__device__ __forceinline__ void ldm4(u32* r, u32 addr) {
    asm volatile("ldmatrix.sync.aligned.m8n8.x4.shared.b16 {%0,%1,%2,%3}, [%4];"
        : "=r"(r[0]), "=r"(r[1]), "=r"(r[2]), "=r"(r[3]) : "r"(addr));
}
__device__ __forceinline__ void ldm4t(u32* r, u32 addr) {
    asm volatile("ldmatrix.sync.aligned.m8n8.x4.trans.shared.b16 {%0,%1,%2,%3}, [%4];"
        : "=r"(r[0]), "=r"(r[1]), "=r"(r[2]), "=r"(r[3]) : "r"(addr));
}
__device__ __forceinline__ void mma_bf16(float* c, const u32* a, u32 b0, u32 b1) {
    asm volatile("mma.sync.aligned.m16n8k16.row.col.f32.bf16.bf16.f32 "
        "{%0,%1,%2,%3}, {%4,%5,%6,%7}, {%8,%9}, {%0,%1,%2,%3};"
        : "+f"(c[0]), "+f"(c[1]), "+f"(c[2]), "+f"(c[3])
        : "r"(a[0]), "r"(a[1]), "r"(a[2]), "r"(a[3]), "r"(b0), "r"(b1));
}
__device__ __forceinline__ u32 swz(u32 b) { return b ^ ((b >> 3) & 0x70); }

__device__ __forceinline__ void hl2(float x, float y, u32& h, u32& l) {
    __nv_bfloat16 hx = __float2bfloat16(x), hy = __float2bfloat16(y);
    __nv_bfloat16 lx = __float2bfloat16(x - __bfloat162float(hx));
    __nv_bfloat16 ly = __float2bfloat16(y - __bfloat162float(hy));
    __nv_bfloat162 hh = __halves2bfloat162(hx, hy), ll = __halves2bfloat162(lx, ly);
    h = *(u32*)&hh; l = *(u32*)&ll;
}
__device__ __forceinline__ void cvt8(float4 a, float4 b2, uint4& h, uint4& l) {
    hl2(a.x, a.y, h.x, l.x); hl2(a.z, a.w, h.y, l.y);
    hl2(b2.x, b2.y, h.z, l.z); hl2(b2.z, b2.w, h.w, l.w);
}

__device__ float g_w[N_W];
__device__ float g_qkv[(size_t)TT * BB * 3 * 512];
__device__ float g_r[(size_t)TT * 512];
__device__ float g_att[(size_t)TT * BB * 512];
__device__ __nv_bfloat16 g_ah[2097152], g_al[2097152];
__device__ __nv_bfloat16 g_wh[1310720], g_wl[1310720];

// ---------------------------------------------------------------------------
__global__ void k_sample_w(const float* __restrict__ mu, const float* __restrict__ rho,
                           const float* __restrict__ eps, float* __restrict__ w,
                           __nv_bfloat16* __restrict__ wh, __nv_bfloat16* __restrict__ wl) {
    int i = blockIdx.x * blockDim.x + threadIdx.x;
    if (i < N_W) {
        float r = rho[i];
        float sp = (r > 20.f) ? r : log1pf(expf(r));
        float v = fmaf(sp, eps[i], mu[i]);
        w[i] = v;
        if (i < 1310720) {
            __nv_bfloat16 h = __float2bfloat16(v);
            wh[i] = h;
            wl[i] = __float2bfloat16(v - __bfloat162float(h));
        }
    }
}

__global__ void k_split(const float* __restrict__ x, __nv_bfloat16* __restrict__ hi,
                        __nv_bfloat16* __restrict__ lo, int n) {
    int i = blockIdx.x * blockDim.x + threadIdx.x;
    if (i < n) {
        float v = x[i];
        __nv_bfloat16 h = __float2bfloat16(v);
        hi[i] = h;
        lo[i] = __float2bfloat16(v - __bfloat162float(h));
    }
}

// ---------------------------------------------------------------------------
// HMMA GEMM (round-10 proven): C = A @ W^T + bias, bf16 hi/lo 3-pass.
// ---------------------------------------------------------------------------
#define GS_AH 0
#define GS_AL 16384
#define GS_BH 32768
#define GS_BL 49152
#define SMEM_G 65536

__global__ __launch_bounds__(256, 2)
void k_hgemm(const __nv_bfloat16* __restrict__ Ah, const __nv_bfloat16* __restrict__ Al,
             const __nv_bfloat16* __restrict__ Wh, const __nv_bfloat16* __restrict__ Wl,
             const float* __restrict__ bias, float* __restrict__ C, int M, int N) {
    extern __shared__ char smem[];
    const u32 sb = s2u(smem);
    const int tid = threadIdx.x, lane = tid & 31, warp = tid >> 5;
    const int m0 = blockIdx.y * 128, n0 = blockIdx.x * 128;
    const int wm = (warp >> 2) * 64, wn = (warp & 3) * 32;
    const int rA = (lane & 7) + ((lane >> 3) & 1) * 8;
    const int cA = ((lane >> 4) & 1) * 16;
    const int rB = (lane & 7) + ((lane >> 4) & 1) * 8;
    const int cB = ((lane >> 3) & 1) * 16;

    float acc[4][4][4];
#pragma unroll
    for (int u = 0; u < 4; u++)
#pragma unroll
        for (int t = 0; t < 4; t++)
#pragma unroll
            for (int e = 0; e < 4; e++) acc[u][t][e] = 0.f;

    for (int c = 0; c < 8; c++) {
        __syncthreads();
#pragma unroll
        for (int p = 0; p < 4; p++) {
            int idx = p * 256 + tid;
            int row = idx >> 3, c8 = idx & 7;
            u32 off = swz(row * 128 + c8 * 16);
            size_t ga = (size_t)(m0 + row) * 512 + c * 64 + c8 * 8;
            size_t gb = (size_t)(n0 + row) * 512 + c * 64 + c8 * 8;
            *(uint4*)(smem + GS_AH + off) = *(const uint4*)(Ah + ga);
            *(uint4*)(smem + GS_AL + off) = *(const uint4*)(Al + ga);
            *(uint4*)(smem + GS_BH + off) = *(const uint4*)(Wh + gb);
            *(uint4*)(smem + GS_BL + off) = *(const uint4*)(Wl + gb);
        }
        __syncthreads();
#pragma unroll
        for (int s = 0; s < 4; s++) {
            u32 ah[4][4], al[4][4];
#pragma unroll
            for (int u = 0; u < 4; u++) {
                u32 off = swz((wm + u * 16 + rA) * 128 + cA + s * 32);
                ldm4(ah[u], sb + GS_AH + off);
                ldm4(al[u], sb + GS_AL + off);
            }
#pragma unroll
            for (int t = 0; t < 2; t++) {
                u32 bh[4], bl[4];
                u32 off = swz((wn + t * 16 + rB) * 128 + cB + s * 32);
                ldm4(bh, sb + GS_BH + off);
                ldm4(bl, sb + GS_BL + off);
#pragma unroll
                for (int h = 0; h < 2; h++) {
                    int n8 = t * 2 + h;
#pragma unroll
                    for (int u = 0; u < 4; u++) {
                        mma_bf16(acc[u][n8], ah[u], bh[2 * h], bh[2 * h + 1]);
                        mma_bf16(acc[u][n8], ah[u], bl[2 * h], bl[2 * h + 1]);
                        mma_bf16(acc[u][n8], al[u], bh[2 * h], bh[2 * h + 1]);
                    }
                }
            }
        }
    }
#pragma unroll
    for (int u = 0; u < 4; u++)
#pragma unroll
        for (int n8 = 0; n8 < 4; n8++) {
            int col = n0 + wn + n8 * 8 + 2 * (lane & 3);
            int row = m0 + wm + u * 16 + (lane >> 2);
            float2 bv = *(const float2*)(bias + col);
            *(float2*)(C + (size_t)row * N + col) =
                make_float2(acc[u][n8][0] + bv.x, acc[u][n8][1] + bv.y);
            *(float2*)(C + (size_t)(row + 8) * N + col) =
                make_float2(acc[u][n8][2] + bv.x, acc[u][n8][3] + bv.y);
        }
}

// ---------------------------------------------------------------------------
// Tensor-core flash attention with fused rel-shift.
// S(64x192) = qw @ [K | R]^T (3-pass bf16 split); gather S1 + S2[dd] + corr[dd];
// SIMT online softmax; PV = P @ V (3-pass, ldmatrix.trans for V).
// ---------------------------------------------------------------------------
#define TF_QWH 0
#define TF_QWL 8192
#define TF_KH  16384
#define TF_KL  24576
#define TF_VH  32768
#define TF_VL  40960
#define TF_RH  49152
#define TF_RL  65536
#define TF_PH  81920
#define TF_PL  90112
#define TF_S   98304
#define TF_SC  148480
#define TF_LI  148736
#define TF_CO  148992
#define TF_DL  149504
#define TF_TOT 149760

__global__ __launch_bounds__(256)
void k_tflash(const float* __restrict__ qkv, const float* __restrict__ rbuf,
              const float* __restrict__ w, float* __restrict__ att) {
    extern __shared__ char smem[];
    float* Sb    = (float*)(smem + TF_S);     // [64][196]
    float* scale = (float*)(smem + TF_SC);
    float* linv  = (float*)(smem + TF_LI);
    float* corr  = (float*)(smem + TF_CO);
    float* delta = (float*)(smem + TF_DL);
    const u32 sb = s2u(smem);
    const int combo = blockIdx.x, b = combo >> 3, n = combo & 7;
    const int it = 31 - (int)blockIdx.y, i0 = it * 64;
    const int tid = threadIdx.x, lane = tid & 31, warp = tid >> 5;
    const int rA = (lane & 7) + ((lane >> 3) & 1) * 8;
    const int cA = ((lane >> 4) & 1) * 16;
    const int rB = (lane & 7) + ((lane >> 4) & 1) * 8;
    const int cB = ((lane >> 3) & 1) * 16;
    const int mi2 = (warp >> 2) * 32;           // warp row-stripe (32)
    const int nc0 = (warp & 3) * 48;            // S cols (48)
    const int d0 = (warp & 3) * 16;             // PV d cols (16)
    const int si = tid >> 2, jg = tid & 3;      // softmax mapping

    if (tid < 64)
        delta[tid] = w[OFF_RRB + n * 64 + tid] - w[OFF_RWB + n * 64 + tid];

    // stage qw = q + rwb (bf16 hi/lo)
#pragma unroll
    for (int p = 0; p < 2; p++) {
        int c = p * 256 + tid;
        int row = c >> 3, c8 = (c & 7) * 8;
        const float* qg = qkv + ((size_t)(i0 + row) * BB + b) * 1536 + n * 64 + c8;
        const float* bg = w + OFF_RWB + n * 64 + c8;
        float4 a = *(const float4*)qg, a2 = *(const float4*)(qg + 4);
        float4 bw = *(const float4*)bg, bw2 = *(const float4*)(bg + 4);
        a.x += bw.x; a.y += bw.y; a.z += bw.z; a.w += bw.w;
        a2.x += bw2.x; a2.y += bw2.y; a2.z += bw2.z; a2.w += bw2.w;
        uint4 h, l; cvt8(a, a2, h, l);
        u32 off = swz(row * 128 + c8 * 2);
        *(uint4*)(smem + TF_QWH + off) = h;
        *(uint4*)(smem + TF_QWL + off) = l;
    }

    float mrun = -1e30f, lrun = 0.f;
    float o[2][2][4];
#pragma unroll
    for (int u = 0; u < 2; u++)
#pragma unroll
        for (int h = 0; h < 2; h++)
#pragma unroll
            for (int e = 0; e < 4; e++) o[u][h][e] = 0.f;

    for (int jt = 0; jt <= it; jt++) {
        const int j0 = jt * 64;
        __syncthreads();
        // stage K, V
#pragma unroll
        for (int p = 0; p < 2; p++) {
            int c = p * 256 + tid;
            int row = c >> 3, c8 = (c & 7) * 8;
            const float* g = qkv + ((size_t)(j0 + row) * BB + b) * 1536 + n * 64 + c8;
            uint4 h, l;
            u32 off = swz(row * 128 + c8 * 2);
            cvt8(*(const float4*)(g + 512), *(const float4*)(g + 516), h, l);
            *(uint4*)(smem + TF_KH + off) = h;
            *(uint4*)(smem + TF_KL + off) = l;
            cvt8(*(const float4*)(g + 1024), *(const float4*)(g + 1028), h, l);
            *(uint4*)(smem + TF_VH + off) = h;
            *(uint4*)(smem + TF_VL + off) = l;
        }
        // stage R band (dd 0..126, row 127 zero)
        const int m_base = j0 - i0 + 1984;
#pragma unroll
        for (int p = 0; p < 4; p++) {
            int c = p * 256 + tid;
            int dd = c >> 3, c8 = (c & 7) * 8;
            int gm = m_base + dd;
            float4 ra = make_float4(0.f, 0.f, 0.f, 0.f), ra2 = ra;
            if (dd < 127 && gm < TT) {
                const float* g = rbuf + (size_t)gm * 512 + n * 64 + c8;
                ra = *(const float4*)g; ra2 = *(const float4*)(g + 4);
            }
            uint4 h, l; cvt8(ra, ra2, h, l);
            u32 off = swz(dd * 128 + c8 * 2);
            *(uint4*)(smem + TF_RH + off) = h;
            *(uint4*)(smem + TF_RL + off) = l;
        }
        // corr[dd] = delta . r_dd  (from gmem, L2-hot)
        if (tid < 127) {
            int gm = m_base + tid;
            float s = 0.f;
            if (gm < TT) {
                const float4* rr = (const float4*)(rbuf + (size_t)gm * 512 + n * 64);
                const float4* dl = (const float4*)delta;
#pragma unroll
                for (int k4 = 0; k4 < 16; k4++) {
                    float4 rv = rr[k4], dv = dl[k4];
                    s = fmaf(dv.x, rv.x, s); s = fmaf(dv.y, rv.y, s);
                    s = fmaf(dv.z, rv.z, s); s = fmaf(dv.w, rv.w, s);
                }
            }
            corr[tid] = s;
        }
        __syncthreads();

        // ---- S GEMM: rows mi2..+31, cols nc0..+47 ----
        float c48[2][6][4];
#pragma unroll
        for (int u = 0; u < 2; u++)
#pragma unroll
            for (int t = 0; t < 6; t++)
#pragma unroll
                for (int e = 0; e < 4; e++) c48[u][t][e] = 0.f;
#pragma unroll
        for (int kk = 0; kk < 4; kk++) {
            u32 ah[2][4], al[2][4];
#pragma unroll
            for (int u = 0; u < 2; u++) {
                u32 off = swz((mi2 + u * 16 + rA) * 128 + cA + kk * 32);
                ldm4(ah[u], sb + TF_QWH + off);
                ldm4(al[u], sb + TF_QWL + off);
            }
#pragma unroll
            for (int nt = 0; nt < 3; nt++) {
                int col0 = nc0 + nt * 16;
                u32 bufh = (col0 < 64) ? TF_KH : TF_RH;
                u32 bufl = (col0 < 64) ? TF_KL : TF_RL;
                int brow = (col0 < 64) ? col0 : col0 - 64;
                u32 bh[4], bl[4];
                u32 off = swz((brow + rB) * 128 + cB + kk * 32);
                ldm4(bh, sb + bufh + off);
                ldm4(bl, sb + bufl + off);
#pragma unroll
                for (int u = 0; u < 2; u++)
#pragma unroll
                    for (int h = 0; h < 2; h++) {
                        float* cc = c48[u][nt * 2 + h];
                        mma_bf16(cc, ah[u], bh[2 * h], bh[2 * h + 1]);
                        mma_bf16(cc, ah[u], bl[2 * h], bl[2 * h + 1]);
                        mma_bf16(cc, al[u], bh[2 * h], bh[2 * h + 1]);
                    }
            }
        }
        // store S fragments
#pragma unroll
        for (int u = 0; u < 2; u++)
#pragma unroll
            for (int t = 0; t < 6; t++) {
                int row = mi2 + u * 16 + (lane >> 2);
                int col = nc0 + t * 8 + (lane & 3) * 2;
                *(float2*)&Sb[row * 196 + col] = make_float2(c48[u][t][0], c48[u][t][1]);
                *(float2*)&Sb[(row + 8) * 196 + col] = make_float2(c48[u][t][2], c48[u][t][3]);
            }
        __syncthreads();

        // ---- softmax: thread handles row si, j in [jg*16, jg*16+16) ----
        {
            float pv[16];
            float mloc = -1e30f;
            const float* srow = Sb + si * 196;
#pragma unroll
            for (int jj = 0; jj < 16; jj++) {
                int j = jg * 16 + jj;
                float v = -1e30f;
                if (jt < it || j <= si) {
                    int dd = j - si + 63;
                    v = 0.125f * (srow[j] + srow[64 + dd] + corr[dd]);
                }
                pv[jj] = v;
                mloc = fmaxf(mloc, v);
            }
            mloc = fmaxf(mloc, __shfl_xor_sync(0xffffffffu, mloc, 1));
            mloc = fmaxf(mloc, __shfl_xor_sync(0xffffffffu, mloc, 2));
            float mnew = fmaxf(mrun, mloc);
            float sc = __expf(mrun - mnew);
            mrun = mnew;
            float ls = 0.f;
            u32 hb[8], lb[8];
#pragma unroll
            for (int q = 0; q < 8; q++) {
                float p0 = (pv[2 * q] > -1e29f) ? __expf(pv[2 * q] - mnew) : 0.f;
                float p1 = (pv[2 * q + 1] > -1e29f) ? __expf(pv[2 * q + 1] - mnew) : 0.f;
                ls += p0 + p1;
                hl2(p0, p1, hb[q], lb[q]);
            }
            ls += __shfl_xor_sync(0xffffffffu, ls, 1);
            ls += __shfl_xor_sync(0xffffffffu, ls, 2);
            lrun = lrun * sc + ls;
            if ((tid & 3) == 0) scale[si] = sc;
            u32 off0 = swz(si * 128 + jg * 32), off1 = swz(si * 128 + jg * 32 + 16);
            *(uint4*)(smem + TF_PH + off0) = make_uint4(hb[0], hb[1], hb[2], hb[3]);
            *(uint4*)(smem + TF_PH + off1) = make_uint4(hb[4], hb[5], hb[6], hb[7]);
            *(uint4*)(smem + TF_PL + off0) = make_uint4(lb[0], lb[1], lb[2], lb[3]);
            *(uint4*)(smem + TF_PL + off1) = make_uint4(lb[4], lb[5], lb[6], lb[7]);
        }
        __syncthreads();

        // ---- PV: rows mi2..+31, d cols d0..+15 ----
#pragma unroll
        for (int u = 0; u < 2; u++) {
            float sA_ = scale[mi2 + u * 16 + (lane >> 2)];
            float sB_ = scale[mi2 + u * 16 + 8 + (lane >> 2)];
#pragma unroll
            for (int h = 0; h < 2; h++) {
                o[u][h][0] *= sA_; o[u][h][1] *= sA_;
                o[u][h][2] *= sB_; o[u][h][3] *= sB_;
            }
        }
#pragma unroll
        for (int kk = 0; kk < 4; kk++) {
            u32 ph[2][4], pl[2][4];
#pragma unroll
            for (int u = 0; u < 2; u++) {
                u32 off = swz((mi2 + u * 16 + rA) * 128 + cA + kk * 32);
                ldm4(ph[u], sb + TF_PH + off);
                ldm4(pl[u], sb + TF_PL + off);
            }
            u32 vh[4], vl[4];
            u32 vo = swz((kk * 16 + rA) * 128 + d0 * 2 + cA);
            ldm4t(vh, sb + TF_VH + vo);
            ldm4t(vl, sb + TF_VL + vo);
#pragma unroll
            for (int u = 0; u < 2; u++)
#pragma unroll
                for (int h = 0; h < 2; h++) {
                    mma_bf16(o[u][h], ph[u], vh[2 * h], vh[2 * h + 1]);
                    mma_bf16(o[u][h], ph[u], vl[2 * h], vl[2 * h + 1]);
                    mma_bf16(o[u][h], pl[u], vh[2 * h], vh[2 * h + 1]);
                }
        }
    }

    if ((tid & 3) == 0) linv[si] = 1.f / lrun;
    __syncthreads();
#pragma unroll
    for (int u = 0; u < 2; u++) {
        int r0 = mi2 + u * 16 + (lane >> 2);
        float i0v = linv[r0], i1v = linv[r0 + 8];
#pragma unroll
        for (int h = 0; h < 2; h++) {
            int col = d0 + h * 8 + (lane & 3) * 2;
            *(float2*)(att + ((size_t)(i0 + r0) * BB + b) * 512 + n * 64 + col) =
                make_float2(o[u][h][0] * i0v, o[u][h][1] * i0v);
            *(float2*)(att + ((size_t)(i0 + r0 + 8) * BB + b) * 512 + n * 64 + col) =
                make_float2(o[u][h][2] * i1v, o[u][h][3] * i1v);
        }
    }
}

// ---------------------------------------------------------------------------
extern "C" void kernel_launch(void* const* d_in, const int* in_sizes, int n_in,
                              void* d_out, int out_size) {
    const float* input = (const float*)d_in[0];
    const float* pos   = (const float*)d_in[1];
    const float* mu    = (const float*)d_in[3];
    const float* rho   = (const float*)d_in[4];
    const float* eps   = (const float*)d_in[5];
    float* out = (float*)d_out;

    float *w, *qkv, *r, *att;
    __nv_bfloat16 *ah, *al, *wh, *wl;
    cudaGetSymbolAddress((void**)&w,   g_w);
    cudaGetSymbolAddress((void**)&qkv, g_qkv);
    cudaGetSymbolAddress((void**)&r,   g_r);
    cudaGetSymbolAddress((void**)&att, g_att);
    cudaGetSymbolAddress((void**)&ah,  g_ah);
    cudaGetSymbolAddress((void**)&al,  g_al);
    cudaGetSymbolAddress((void**)&wh,  g_wh);
    cudaGetSymbolAddress((void**)&wl,  g_wl);

    static bool attr_set = false;
    if (!attr_set) {
        cudaFuncSetAttribute(k_hgemm, cudaFuncAttributeMaxDynamicSharedMemorySize, SMEM_G);
        cudaFuncSetAttribute(k_tflash, cudaFuncAttributeMaxDynamicSharedMemorySize, TF_TOT);
        attr_set = true;
    }

    k_sample_w<<<(N_W + 255) / 256, 256>>>(mu, rho, eps, w, wh, wl);

    k_split<<<(2097152 + 255) / 256, 256>>>(input, ah, al, 2097152);
    k_hgemm<<<dim3(12, 32), 256, SMEM_G>>>(ah, al, wh + OFF_INW, wl + OFF_INW,
                                           w + OFF_INB, qkv, 4096, 1536);
    k_split<<<(1048576 + 255) / 256, 256>>>(pos, ah, al, 1048576);
    k_hgemm<<<dim3(4, 16), 256, SMEM_G>>>(ah, al, wh + OFF_POSW, wl + OFF_POSW,
                                          w + OFF_POSB, r, 2048, 512);

    k_tflash<<<dim3(BB * NHH, 32), 256, TF_TOT>>>(qkv, r, w, att);

    k_split<<<(2097152 + 255) / 256, 256>>>(att, ah, al, 2097152);
    k_hgemm<<<dim3(4, 32), 256, SMEM_G>>>(ah, al, wh + OFF_OUTW, wl + OFF_OUTW,
                                          w + OFF_OUTB, out, 4096, 512);
}